// round 10
// baseline (speedup 1.0000x reference)
#include <cuda_runtime.h>
#include <cuda_fp16.h>
#include <cstdint>

#define N_USERS 100000
#define N_ITEMS 60000
#define N_NODES (N_USERS + N_ITEMS)
#define EMB_DIM 128
#define VEC (EMB_DIM / 4)        // 32 float4 chunks per fp32 row
#define ROW16 (EMB_DIM / 8)      // 16 uint4 chunks per fp16 row (16B each)
#define N_EDGES 1500000

// Scratch (__device__ globals per allocation-free rule)
__device__ uint4 g_x0h[(size_t)N_NODES * ROW16];
__device__ uint4 g_x1[(size_t)N_NODES * ROW16];
__device__ uint4 g_x2[(size_t)N_NODES * ROW16];
__device__ float g_invdeg[N_NODES];
__device__ int   g_deg[N_NODES];
__device__ int   g_rowptr[N_NODES];
__device__ int   g_cursor[N_NODES];
__device__ int   g_csr[N_EDGES];
__device__ int   g_counter[1];

// ---------------------------------------------------------------------------
__device__ __forceinline__ __half2 h2(uint32_t b) {
    return *reinterpret_cast<__half2*>(&b);
}
__device__ __forceinline__ uint32_t pack2(float a, float b) {
    __half2 p = __floats2half2_rn(a, b);
    return *reinterpret_cast<uint32_t*>(&p);
}
__device__ __forceinline__ void addf2(float2& a, __half2 v) {
    float2 f = __half22float2(v);
    a.x += f.x; a.y += f.y;
}

// 1) fused: convert concat(ue,ie) fp32->fp16 table  +  dst degree histogram
//    fp16 row chunk i (uint4, 8 halfs) <- fp32 float4 chunks 2i, 2i+1
__global__ void convhist_kernel(const float4* __restrict__ ue,
                                const float4* __restrict__ ie,
                                uint4* __restrict__ x0h,
                                const int* __restrict__ dst,
                                int* __restrict__ deg) {
    long i = (long)blockIdx.x * blockDim.x + threadIdx.x;
    const long total = (long)N_NODES * ROW16;      // 2,560,000
    if (i < total) {
        const long user_lim = (long)N_USERS * ROW16;
        const float4* srcp = (i < user_lim) ? (ue + 2 * i)
                                            : (ie + 2 * (i - user_lim));
        float4 a = __ldcs(&srcp[0]);
        float4 b = __ldcs(&srcp[1]);
        uint4 o;
        o.x = pack2(a.x, a.y); o.y = pack2(a.z, a.w);
        o.z = pack2(b.x, b.y); o.w = pack2(b.z, b.w);
        __stcs(&x0h[i], o);
    }
    if (i < N_EDGES) atomicAdd(&deg[dst[(int)i]], 1);
}

// 2) segment assignment via global cursor (replaces prefix scan) + invdeg
__global__ void assign_kernel(const int* __restrict__ deg,
                              int* __restrict__ rowptr,
                              int* __restrict__ cursor,
                              float* __restrict__ invdeg,
                              int* __restrict__ counter) {
    int v = blockIdx.x * blockDim.x + threadIdx.x;
    if (v >= N_NODES) return;
    int d = deg[v];
    int beg = (d > 0) ? atomicAdd(counter, d) : 0;
    rowptr[v] = beg;
    cursor[v] = beg;
    invdeg[v] = (d > 0) ? (1.0f / (float)d) : 0.0f;
}

// 3) bin edges by dst into the assigned segments
__global__ void permute_kernel(const int* __restrict__ src,
                               const int* __restrict__ dst,
                               int* __restrict__ cursor,
                               int* __restrict__ csr) {
    int e = blockIdx.x * blockDim.x + threadIdx.x;
    if (e < N_EDGES) {
        int pos = atomicAdd(&cursor[dst[e]], 1);
        csr[pos] = src[e];
    }
}

// ---------------------------------------------------------------------------
// Half-warp-per-node mean: lane q in [0,16) owns 16 bytes (4 half2) of the
// 256B fp16 row; two nodes per warp (divergent trip counts, predicated).
// 4-edge unroll, depth-2 HADD2 tree, fp32 group accumulation.
__device__ __forceinline__ void halfwarp_mean(const int* __restrict__ rowptr,
                                              const int* __restrict__ deg,
                                              const int* __restrict__ csr,
                                              const float* __restrict__ invdeg,
                                              const uint4* __restrict__ xin,
                                              int n, int q,
                                              float2& f0, float2& f1,
                                              float2& f2, float2& f3) {
    int beg = __ldg(&rowptr[n]);
    int end = beg + __ldg(&deg[n]);
    f0 = {0.f, 0.f}; f1 = {0.f, 0.f}; f2 = {0.f, 0.f}; f3 = {0.f, 0.f};
    int i = beg;
    for (; i + 3 < end; i += 4) {
        int s0 = __ldg(&csr[i]),   s1 = __ldg(&csr[i+1]);
        int s2 = __ldg(&csr[i+2]), s3 = __ldg(&csr[i+3]);
        uint4 u0 = __ldg(&xin[(long)s0 * ROW16 + q]);
        uint4 u1 = __ldg(&xin[(long)s1 * ROW16 + q]);
        uint4 u2 = __ldg(&xin[(long)s2 * ROW16 + q]);
        uint4 u3 = __ldg(&xin[(long)s3 * ROW16 + q]);
        __half2 t0 = __hadd2(__hadd2(h2(u0.x), h2(u1.x)),
                             __hadd2(h2(u2.x), h2(u3.x)));
        __half2 t1 = __hadd2(__hadd2(h2(u0.y), h2(u1.y)),
                             __hadd2(h2(u2.y), h2(u3.y)));
        __half2 t2 = __hadd2(__hadd2(h2(u0.z), h2(u1.z)),
                             __hadd2(h2(u2.z), h2(u3.z)));
        __half2 t3 = __hadd2(__hadd2(h2(u0.w), h2(u1.w)),
                             __hadd2(h2(u2.w), h2(u3.w)));
        addf2(f0, t0); addf2(f1, t1); addf2(f2, t2); addf2(f3, t3);
    }
    for (; i < end; ++i) {
        int s = __ldg(&csr[i]);
        uint4 u = __ldg(&xin[(long)s * ROW16 + q]);
        addf2(f0, h2(u.x)); addf2(f1, h2(u.y));
        addf2(f2, h2(u.z)); addf2(f3, h2(u.w));
    }
    float sc = __ldg(&invdeg[n]);
    f0.x *= sc; f0.y *= sc; f1.x *= sc; f1.y *= sc;
    f2.x *= sc; f2.y *= sc; f3.x *= sc; f3.y *= sc;
}

// Layers 1 & 2: xout (fp16) = A~ @ xin (fp16). Two nodes per warp.
__global__ void __launch_bounds__(256)
layer_kernel(const int* __restrict__ rowptr, const int* __restrict__ deg,
             const int* __restrict__ csr, const float* __restrict__ invdeg,
             const uint4* __restrict__ xin, uint4* __restrict__ xout) {
    int warp = (blockIdx.x * blockDim.x + threadIdx.x) >> 5;
    int lane = threadIdx.x & 31;
    int n = warp * 2 + (lane >> 4);
    int q = lane & 15;
    if (n >= N_NODES) return;
    float2 f0, f1, f2, f3;
    halfwarp_mean(rowptr, deg, csr, invdeg, xin, n, q, f0, f1, f2, f3);
    uint4 o;
    o.x = pack2(f0.x, f0.y); o.y = pack2(f1.x, f1.y);
    o.z = pack2(f2.x, f2.y); o.w = pack2(f3.x, f3.y);
    xout[(long)n * ROW16 + q] = o;   // next layer's gather table: keep in L2
}

// Layer 3 fused finale: r = A~ @ x2 (regs only); out = 0.25*(x0_fp32+x1+x2+r)
// Lane q owns fp32 row elements [8q, 8q+8) = float4 chunks 2q, 2q+1.
__global__ void __launch_bounds__(256)
layer3_kernel(const int* __restrict__ rowptr, const int* __restrict__ deg,
              const int* __restrict__ csr, const float* __restrict__ invdeg,
              const float4* __restrict__ ue, const float4* __restrict__ ie,
              const uint4* __restrict__ x1, const uint4* __restrict__ x2,
              float4* __restrict__ out) {
    int warp = (blockIdx.x * blockDim.x + threadIdx.x) >> 5;
    int lane = threadIdx.x & 31;
    int n = warp * 2 + (lane >> 4);
    int q = lane & 15;
    if (n >= N_NODES) return;
    float2 f0, f1, f2, f3;
    halfwarp_mean(rowptr, deg, csr, invdeg, x2, n, q, f0, f1, f2, f3);

    long c16 = (long)n * ROW16 + q;              // fp16 chunk index
    const float4* x0p = (n < N_USERS) ? (ue + ((long)n * VEC + 2 * q))
                                      : (ie + ((long)(n - N_USERS) * VEC + 2 * q));
    float4 a0 = __ldcs(&x0p[0]);                  // x0 fp32 (full precision)
    float4 a1 = __ldcs(&x0p[1]);
    uint4 v1 = __ldcs(&x1[c16]);
    uint4 v2 = __ldg(&x2[c16]);                   // hot in L2 (gather table)

    float2 w1, w2;
    float4 o0, o1;
    w1 = __half22float2(h2(v1.x)); w2 = __half22float2(h2(v2.x));
    o0.x = 0.25f * (a0.x + w1.x + w2.x + f0.x);
    o0.y = 0.25f * (a0.y + w1.y + w2.y + f0.y);
    w1 = __half22float2(h2(v1.y)); w2 = __half22float2(h2(v2.y));
    o0.z = 0.25f * (a0.z + w1.x + w2.x + f1.x);
    o0.w = 0.25f * (a0.w + w1.y + w2.y + f1.y);
    w1 = __half22float2(h2(v1.z)); w2 = __half22float2(h2(v2.z));
    o1.x = 0.25f * (a1.x + w1.x + w2.x + f2.x);
    o1.y = 0.25f * (a1.y + w1.y + w2.y + f2.y);
    w1 = __half22float2(h2(v1.w)); w2 = __half22float2(h2(v2.w));
    o1.z = 0.25f * (a1.z + w1.x + w2.x + f3.x);
    o1.w = 0.25f * (a1.w + w1.y + w2.y + f3.y);

    long c32 = (long)n * VEC + 2 * q;             // fp32 float4 chunk index
    __stcs(&out[c32],     o0);
    __stcs(&out[c32 + 1], o1);
}

extern "C" void kernel_launch(void* const* d_in, const int* in_sizes, int n_in,
                              void* d_out, int out_size) {
    const float* ue = (const float*)d_in[0];           // [N_USERS, 128]
    const float* ie = (const float*)d_in[1];           // [N_ITEMS, 128]
    const int*   ei = (const int*)d_in[2];             // [2, N_EDGES] int32
    const int* src = ei;
    const int* dst = ei + N_EDGES;
    float* out = (float*)d_out;                        // [N_NODES, 128] fp32

    uint4 *x0h, *x1, *x2;
    float *invdeg;
    int *deg, *rowptr, *cursor, *csr, *counter;
    cudaGetSymbolAddress((void**)&x0h, g_x0h);
    cudaGetSymbolAddress((void**)&x1, g_x1);
    cudaGetSymbolAddress((void**)&x2, g_x2);
    cudaGetSymbolAddress((void**)&invdeg, g_invdeg);
    cudaGetSymbolAddress((void**)&deg, g_deg);
    cudaGetSymbolAddress((void**)&rowptr, g_rowptr);
    cudaGetSymbolAddress((void**)&cursor, g_cursor);
    cudaGetSymbolAddress((void**)&csr, g_csr);
    cudaGetSymbolAddress((void**)&counter, g_counter);

    const int BT = 256;
    const long nconv = (long)N_NODES * ROW16;          // 2,560,000

    // ---- CSR build (scan-free) + x0 fp16 conversion ----
    cudaMemsetAsync(deg, 0, N_NODES * sizeof(int));
    cudaMemsetAsync(counter, 0, sizeof(int));
    convhist_kernel<<<(int)((nconv + BT - 1) / BT), BT>>>(
        (const float4*)ue, (const float4*)ie, x0h, dst, deg);
    assign_kernel<<<(N_NODES + BT - 1) / BT, BT>>>(deg, rowptr, cursor,
                                                   invdeg, counter);
    permute_kernel<<<(N_EDGES + BT - 1) / BT, BT>>>(src, dst, cursor, csr);

    // ---- 3 propagation layers (two nodes per warp); layer1 = 4th launch ----
    const int nwarps = N_NODES / 2;                    // 80000
    const int blocks = (nwarps * 32 + BT - 1) / BT;    // 10000
    layer_kernel<<<blocks, BT>>>(rowptr, deg, csr, invdeg, x0h, x1);
    layer_kernel<<<blocks, BT>>>(rowptr, deg, csr, invdeg, x1, x2);
    layer3_kernel<<<blocks, BT>>>(rowptr, deg, csr, invdeg,
                                  (const float4*)ue, (const float4*)ie,
                                  x1, x2, (float4*)out);
}

// round 12
// speedup vs baseline: 1.0637x; 1.0637x over previous
#include <cuda_runtime.h>
#include <cuda_fp16.h>
#include <cstdint>

#define N_USERS 100000
#define N_ITEMS 60000
#define N_NODES (N_USERS + N_ITEMS)
#define EMB_DIM 128
#define VEC (EMB_DIM / 4)        // 32 chunks/row: float4 (fp32) or uint2 (fp16x4)
#define N_EDGES 1500000

static_assert((N_EDGES & 1) == 0, "permute int2 path requires even N_EDGES");

// Scratch (__device__ globals per allocation-free rule)
__device__ uint2 g_x0h[(size_t)N_NODES * VEC];
__device__ uint2 g_x1[(size_t)N_NODES * VEC];
__device__ uint2 g_x2[(size_t)N_NODES * VEC];
__device__ float g_invdeg[N_NODES];
__device__ int   g_deg[N_NODES];
__device__ int   g_rowptr[N_NODES];
__device__ int   g_cursor[N_NODES];
__device__ int   g_csr[N_EDGES];
__device__ int   g_counter[1];

// ---------------------------------------------------------------------------
__device__ __forceinline__ __half2 h2(uint32_t b) {
    return *reinterpret_cast<__half2*>(&b);
}
__device__ __forceinline__ float4 h4_to_f4(uint2 u) {
    float2 lo = __half22float2(h2(u.x));
    float2 hi = __half22float2(h2(u.y));
    float4 r; r.x = lo.x; r.y = lo.y; r.z = hi.x; r.w = hi.y;
    return r;
}
__device__ __forceinline__ uint2 f4_to_h4(float4 v) {
    __half2 lo = __floats2half2_rn(v.x, v.y);
    __half2 hi = __floats2half2_rn(v.z, v.w);
    uint2 u;
    u.x = *reinterpret_cast<uint32_t*>(&lo);
    u.y = *reinterpret_cast<uint32_t*>(&hi);
    return u;
}

// 1) fused: convert concat(ue,ie) fp32->fp16 table  +  dst degree histogram
__global__ void convhist_kernel(const float4* __restrict__ ue,
                                const float4* __restrict__ ie,
                                uint2* __restrict__ x0h,
                                const int* __restrict__ dst,
                                int* __restrict__ deg) {
    long i = (long)blockIdx.x * blockDim.x + threadIdx.x;
    const long total = (long)N_NODES * VEC;        // 5,120,000
    if (i < total) {
        const long user_lim = (long)N_USERS * VEC;
        float4 v = (i < user_lim) ? __ldcs(&ue[i]) : __ldcs(&ie[i - user_lim]);
        __stcs(&x0h[i], f4_to_h4(v));
    }
    if (i < N_EDGES) atomicAdd(&deg[dst[(int)i]], 1);
}

// 2) segment assignment via global cursor (replaces prefix scan) + invdeg
__global__ void assign_kernel(const int* __restrict__ deg,
                              int* __restrict__ rowptr,
                              int* __restrict__ cursor,
                              float* __restrict__ invdeg,
                              int* __restrict__ counter) {
    int v = blockIdx.x * blockDim.x + threadIdx.x;
    if (v >= N_NODES) return;
    int d = deg[v];
    int beg = (d > 0) ? atomicAdd(counter, d) : 0;
    rowptr[v] = beg;
    cursor[v] = beg;
    invdeg[v] = (d > 0) ? (1.0f / (float)d) : 0.0f;
}

// 3) bin edges by dst; two edges per thread (int2 index loads)
__global__ void permute_kernel(const int2* __restrict__ src2,
                               const int2* __restrict__ dst2,
                               int* __restrict__ cursor,
                               int* __restrict__ csr) {
    int t = blockIdx.x * blockDim.x + threadIdx.x;
    if (t >= N_EDGES / 2) return;                  // N_EDGES is even
    int2 s = __ldg(&src2[t]);
    int2 d = __ldg(&dst2[t]);
    int p0 = atomicAdd(&cursor[d.x], 1);
    csr[p0] = s.x;
    int p1 = atomicAdd(&cursor[d.y], 1);
    csr[p1] = s.y;
}

// ---------------------------------------------------------------------------
// Warp-per-node mean over an fp16 table (lane owns uint2 = 4 halfs).
// 8-edge unroll reduced FULLY in fp16 (depth-3 HADD2 tree, 14 HADD2 per lane),
// one convert per half2 chunk, fp32 cross-group accumulation.
__device__ __forceinline__ float4 row_mean_h(const int* __restrict__ rowptr,
                                             const int* __restrict__ deg,
                                             const int* __restrict__ csr,
                                             const float* __restrict__ invdeg,
                                             const uint2* __restrict__ xin,
                                             int w, int lane) {
    int beg = __ldg(&rowptr[w]);
    int end = beg + __ldg(&deg[w]);
    float2 aLo = {0.f, 0.f}, aHi = {0.f, 0.f};
    int i = beg;
    for (; i + 7 < end; i += 8) {
        int s0 = csr[i],   s1 = csr[i+1], s2 = csr[i+2], s3 = csr[i+3];
        int s4 = csr[i+4], s5 = csr[i+5], s6 = csr[i+6], s7 = csr[i+7];
        uint2 u0 = __ldg(&xin[(long)s0 * VEC + lane]);
        uint2 u1 = __ldg(&xin[(long)s1 * VEC + lane]);
        uint2 u2 = __ldg(&xin[(long)s2 * VEC + lane]);
        uint2 u3 = __ldg(&xin[(long)s3 * VEC + lane]);
        uint2 u4 = __ldg(&xin[(long)s4 * VEC + lane]);
        uint2 u5 = __ldg(&xin[(long)s5 * VEC + lane]);
        uint2 u6 = __ldg(&xin[(long)s6 * VEC + lane]);
        uint2 u7 = __ldg(&xin[(long)s7 * VEC + lane]);
        // depth-3 fp16 tree over all 8 edges, per half2 chunk
        __half2 tL = __hadd2(__hadd2(__hadd2(h2(u0.x), h2(u1.x)),
                                     __hadd2(h2(u2.x), h2(u3.x))),
                             __hadd2(__hadd2(h2(u4.x), h2(u5.x)),
                                     __hadd2(h2(u6.x), h2(u7.x))));
        __half2 tH = __hadd2(__hadd2(__hadd2(h2(u0.y), h2(u1.y)),
                                     __hadd2(h2(u2.y), h2(u3.y))),
                             __hadd2(__hadd2(h2(u4.y), h2(u5.y)),
                                     __hadd2(h2(u6.y), h2(u7.y))));
        float2 f;
        f = __half22float2(tL); aLo.x += f.x; aLo.y += f.y;
        f = __half22float2(tH); aHi.x += f.x; aHi.y += f.y;
    }
    for (; i + 3 < end; i += 4) {
        int s0 = csr[i], s1 = csr[i+1], s2 = csr[i+2], s3 = csr[i+3];
        uint2 u0 = __ldg(&xin[(long)s0 * VEC + lane]);
        uint2 u1 = __ldg(&xin[(long)s1 * VEC + lane]);
        uint2 u2 = __ldg(&xin[(long)s2 * VEC + lane]);
        uint2 u3 = __ldg(&xin[(long)s3 * VEC + lane]);
        __half2 tL = __hadd2(__hadd2(h2(u0.x), h2(u1.x)),
                             __hadd2(h2(u2.x), h2(u3.x)));
        __half2 tH = __hadd2(__hadd2(h2(u0.y), h2(u1.y)),
                             __hadd2(h2(u2.y), h2(u3.y)));
        float2 f;
        f = __half22float2(tL); aLo.x += f.x; aLo.y += f.y;
        f = __half22float2(tH); aHi.x += f.x; aHi.y += f.y;
    }
    for (; i < end; ++i) {               // <=3 remainders in fp32
        int s = csr[i];
        float4 v = h4_to_f4(__ldg(&xin[(long)s * VEC + lane]));
        aLo.x += v.x; aLo.y += v.y; aHi.x += v.z; aHi.y += v.w;
    }
    float sc = __ldg(&invdeg[w]);
    float4 r;
    r.x = aLo.x * sc; r.y = aLo.y * sc;
    r.z = aHi.x * sc; r.w = aHi.y * sc;
    return r;
}

// Layers 1 & 2: xout (fp16) = A~ @ xin (fp16)
__global__ void __launch_bounds__(256)
layer_kernel(const int* __restrict__ rowptr, const int* __restrict__ deg,
             const int* __restrict__ csr, const float* __restrict__ invdeg,
             const uint2* __restrict__ xin, uint2* __restrict__ xout) {
    int w = (blockIdx.x * blockDim.x + threadIdx.x) >> 5;
    int lane = threadIdx.x & 31;
    if (w >= N_NODES) return;
    float4 r = row_mean_h(rowptr, deg, csr, invdeg, xin, w, lane);
    xout[(long)w * VEC + lane] = f4_to_h4(r);   // next gather table: keep in L2
}

// Layer 3 fused finale: r = A~ @ x2 (regs only); out = 0.25*(x0_fp32+x1+x2+r)
__global__ void __launch_bounds__(256)
layer3_kernel(const int* __restrict__ rowptr, const int* __restrict__ deg,
              const int* __restrict__ csr, const float* __restrict__ invdeg,
              const float4* __restrict__ ue, const float4* __restrict__ ie,
              const uint2* __restrict__ x1, const uint2* __restrict__ x2,
              float4* __restrict__ out) {
    int w = (blockIdx.x * blockDim.x + threadIdx.x) >> 5;
    int lane = threadIdx.x & 31;
    if (w >= N_NODES) return;
    float4 r = row_mean_h(rowptr, deg, csr, invdeg, x2, w, lane);
    long o = (long)w * VEC + lane;
    float4 v0 = (w < N_USERS) ? __ldcs(&ue[o]) : __ldcs(&ie[o - (long)N_USERS * VEC]);
    float4 v1 = h4_to_f4(__ldcs(&x1[o]));
    float4 v2 = h4_to_f4(__ldg(&x2[o]));      // hot in L2 (gather table)
    float4 ov;
    ov.x = 0.25f * (v0.x + v1.x + v2.x + r.x);
    ov.y = 0.25f * (v0.y + v1.y + v2.y + r.y);
    ov.z = 0.25f * (v0.z + v1.z + v2.z + r.z);
    ov.w = 0.25f * (v0.w + v1.w + v2.w + r.w);
    __stcs(&out[o], ov);
}

extern "C" void kernel_launch(void* const* d_in, const int* in_sizes, int n_in,
                              void* d_out, int out_size) {
    const float* ue = (const float*)d_in[0];           // [N_USERS, 128]
    const float* ie = (const float*)d_in[1];           // [N_ITEMS, 128]
    const int*   ei = (const int*)d_in[2];             // [2, N_EDGES] int32
    const int* src = ei;
    const int* dst = ei + N_EDGES;
    float* out = (float*)d_out;                        // [N_NODES, 128] fp32

    uint2 *x0h, *x1, *x2;
    float *invdeg;
    int *deg, *rowptr, *cursor, *csr, *counter;
    cudaGetSymbolAddress((void**)&x0h, g_x0h);
    cudaGetSymbolAddress((void**)&x1, g_x1);
    cudaGetSymbolAddress((void**)&x2, g_x2);
    cudaGetSymbolAddress((void**)&invdeg, g_invdeg);
    cudaGetSymbolAddress((void**)&deg, g_deg);
    cudaGetSymbolAddress((void**)&rowptr, g_rowptr);
    cudaGetSymbolAddress((void**)&cursor, g_cursor);
    cudaGetSymbolAddress((void**)&csr, g_csr);
    cudaGetSymbolAddress((void**)&counter, g_counter);

    const int BT = 256;
    const long nvec = (long)N_NODES * VEC;             // 5,120,000

    // ---- CSR build (scan-free) + x0 fp16 conversion ----
    cudaMemsetAsync(deg, 0, N_NODES * sizeof(int));
    cudaMemsetAsync(counter, 0, sizeof(int));
    convhist_kernel<<<(int)((nvec + BT - 1) / BT), BT>>>(
        (const float4*)ue, (const float4*)ie, x0h, dst, deg);
    assign_kernel<<<(N_NODES + BT - 1) / BT, BT>>>(deg, rowptr, cursor,
                                                   invdeg, counter);
    permute_kernel<<<(N_EDGES / 2 + BT - 1) / BT, BT>>>(
        (const int2*)src, (const int2*)dst, cursor, csr);

    // ---- 3 propagation layers (warp per node); layer1 = 4th launch -> ncu ----
    const int blocks = (N_NODES * 32 + BT - 1) / BT;
    layer_kernel<<<blocks, BT>>>(rowptr, deg, csr, invdeg, x0h, x1);
    layer_kernel<<<blocks, BT>>>(rowptr, deg, csr, invdeg, x1, x2);
    layer3_kernel<<<blocks, BT>>>(rowptr, deg, csr, invdeg,
                                  (const float4*)ue, (const float4*)ie,
                                  x1, x2, (float4*)out);
}